// round 17
// baseline (speedup 1.0000x reference)
#include <cuda_runtime.h>
#include <math.h>

#define Bb 64
#define Nn 1024
#define Hh 64
#define Tt 10

// ---------------- scratch (device globals; permuted row space) -----------------
__device__ __align__(16) float g_nrmP[Bb*Nn*Hh];   // emb/||emb||, bucket order
__device__ __align__(16) float g_xw0 [Bb*Nn*Hh];   // emb @ W0^T
__device__ __align__(16) float g_xw1 [Bb*Nn*Hh];   // h1  @ W1^T
__device__ __align__(16) float g_h2P [Bb*Nn*Hh];
__device__ __align__(16) float g_G   [Bb*Tt*Hh*Hh];
__device__ __align__(16) float g_M   [Bb*Tt*Hh*Hh];
__device__ int g_pos[Bb*Nn];
__device__ int g_off[Bb*Tt];
__device__ int g_cnt[Bb*Tt];
__device__ __align__(16) float g_ctx[Bb*Hh];

#define FMA4(A, s, v) { (A).x += (s)*(v).x; (A).y += (s)*(v).y; (A).z += (s)*(v).z; (A).w += (s)*(v).w; }
#define GDC_WAIT()   asm volatile("griddepcontrol.wait;" ::: "memory")
#define GDC_LAUNCH() asm volatile("griddepcontrol.launch_dependents;" ::: "memory")

__device__ __forceinline__ unsigned sm32(const void* p) {
    unsigned a;
    asm("{ .reg .u64 t; cvta.to.shared.u64 t, %1; cvt.u32.u64 %0, t; }"
        : "=r"(a) : "l"(p));
    return a;
}
__device__ __forceinline__ void cpa16(unsigned dst, const void* src, int sz) {
    asm volatile("cp.async.ca.shared.global [%0], [%1], 16, %2;"
                 :: "r"(dst), "l"(src), "r"(sz));
}
#define CP_COMMIT() asm volatile("cp.async.commit_group;" ::: "memory")
#define CP_WAIT1()  asm volatile("cp.async.wait_group 1;" ::: "memory")

// ---------------- K1: enc (+in-block bucket) -> nrmP, HW0, pos/off/cnt ----------
__global__ __launch_bounds__(256) void k_enc(
    const float* __restrict__ tf, const int* __restrict__ types,
    const float* __restrict__ w1, const float* __restrict__ b1,
    const float* __restrict__ w2, const float* __restrict__ b2,
    const float* __restrict__ gw)
{
    __shared__ __align__(16) float s_A[64*68];
    __shared__ __align__(16) float s_B[64*68];
    __shared__ int   s_types[1024];
    __shared__ int   s_cnt16[16];
    __shared__ int   s_off16[16];
    __shared__ short s_rankp[64][4];
    __shared__ int   s_posl[64];
    __shared__ __align__(16) float s_f[192];
    __shared__ __align__(16) float s_w1[192];
    __shared__ __align__(16) float s_b1[64];
    __shared__ __align__(16) float s_b2[64];
    int tid = threadIdx.x;
    int tx = tid & 15, ty = tid >> 4;
    int b = blockIdx.x >> 4, seg = blockIdx.x & 15;
    int base = blockIdx.x * 64;

    // ---- in-block bucket: counts, offsets, ranks for my 64 rows ----
    #pragma unroll
    for (int i = tid; i < 1024; i += 256) s_types[i] = types[b*Nn + i];
    if (tid < 16) s_cnt16[tid] = 0;
    __syncthreads();
    #pragma unroll
    for (int i = tid; i < 1024; i += 256) atomicAdd(&s_cnt16[s_types[i]], 1);
    __syncthreads();
    if (tid == 0) {
        int a = 0;
        #pragma unroll
        for (int t = 0; t < Tt; ++t) { s_off16[t] = a; a += s_cnt16[t]; }
    }
    __syncthreads();
    {
        int r = tid >> 2, q = tid & 3;
        int n = seg*64 + r;
        int tn = s_types[n];
        int lo = q << 8, hi = n < lo + 256 ? n : lo + 256;
        int c = 0;
        for (int m = lo; m < hi; ++m) c += (s_types[m] == tn);
        s_rankp[r][q] = (short)c;
    }
    // weight staging overlapped with rank reduce
    #pragma unroll
    for (int it = 0; it < 16; ++it) {
        int e = tid + it*256;
        int j = e >> 6, k = e & 63;
        s_B[k*68 + j] = w2[e];                 // w2^T
    }
    if (tid < 192) { s_f[tid] = tf[base*3 + tid]; s_w1[tid] = w1[tid]; }
    if (tid < 64)  { s_b1[tid] = b1[tid]; s_b2[tid] = b2[tid]; }
    __syncthreads();
    if (tid < 64) {
        int n = seg*64 + tid;
        int rank = s_rankp[tid][0] + s_rankp[tid][1] + s_rankp[tid][2] + s_rankp[tid][3];
        int pos = b*Nn + s_off16[s_types[n]] + rank;
        s_posl[tid] = pos;
        g_pos[b*Nn + n] = pos;
    }
    if (seg == 0) {
        if (tid < Tt) { g_cnt[b*Tt + tid] = s_cnt16[tid]; g_off[b*Tt + tid] = s_off16[tid]; }
        if (tid < 64) g_ctx[b*64 + tid] = 0.f;
    }

    // ---- encoder ----
    #pragma unroll
    for (int it = 0; it < 16; ++it) {
        int e = tid + it*256;
        int row = e >> 6, k = e & 63;
        float h = s_f[row*3+0]*s_w1[k*3+0] + s_f[row*3+1]*s_w1[k*3+1]
                + s_f[row*3+2]*s_w1[k*3+2] + s_b1[k];
        s_A[row*68 + k] = fmaxf(h, 0.f);
    }
    __syncthreads();

    // emb = h1 @ w2^T + b2
    float4 acc[4];
    #pragma unroll
    for (int i = 0; i < 4; ++i) acc[i] = make_float4(0.f,0.f,0.f,0.f);
    #pragma unroll 8
    for (int kk = 0; kk < 64; ++kk) {
        float4 bb = *(const float4*)&s_B[kk*68 + tx*4];
        float a0 = s_A[(ty*4+0)*68 + kk];
        float a1 = s_A[(ty*4+1)*68 + kk];
        float a2 = s_A[(ty*4+2)*68 + kk];
        float a3 = s_A[(ty*4+3)*68 + kk];
        FMA4(acc[0], a0, bb); FMA4(acc[1], a1, bb);
        FMA4(acc[2], a2, bb); FMA4(acc[3], a3, bb);
    }
    float4 bias = *(const float4*)&s_b2[tx*4];
    int p[4];
    #pragma unroll
    for (int i = 0; i < 4; ++i) {
        acc[i].x += bias.x; acc[i].y += bias.y;
        acc[i].z += bias.z; acc[i].w += bias.w;
        float sq = acc[i].x*acc[i].x + acc[i].y*acc[i].y
                 + acc[i].z*acc[i].z + acc[i].w*acc[i].w;
        #pragma unroll
        for (int o = 8; o > 0; o >>= 1) sq += __shfl_xor_sync(0xffffffffu, sq, o);
        float inv = 1.f / fmaxf(sqrtf(sq), 1e-12f);
        p[i] = s_posl[ty*4 + i];
        float4 nv = make_float4(acc[i].x*inv, acc[i].y*inv, acc[i].z*inv, acc[i].w*inv);
        *(float4*)&g_nrmP[p[i]*64 + tx*4] = nv;
    }
    __syncthreads();

    #pragma unroll
    for (int i = 0; i < 4; ++i)
        *(float4*)&s_A[(ty*4+i)*68 + tx*4] = acc[i];
    #pragma unroll
    for (int it = 0; it < 16; ++it) {
        int e = tid + it*256;
        int c = e >> 6, k = e & 63;
        s_B[k*68 + c] = gw[e];                 // W0^T
    }
    __syncthreads();

    // HW0 = emb @ W0^T (no bias)
    float4 acc2[4];
    #pragma unroll
    for (int i = 0; i < 4; ++i) acc2[i] = make_float4(0.f,0.f,0.f,0.f);
    #pragma unroll 8
    for (int kk = 0; kk < 64; ++kk) {
        float4 bb = *(const float4*)&s_B[kk*68 + tx*4];
        float a0 = s_A[(ty*4+0)*68 + kk];
        float a1 = s_A[(ty*4+1)*68 + kk];
        float a2 = s_A[(ty*4+2)*68 + kk];
        float a3 = s_A[(ty*4+3)*68 + kk];
        FMA4(acc2[0], a0, bb); FMA4(acc2[1], a1, bb);
        FMA4(acc2[2], a2, bb); FMA4(acc2[3], a3, bb);
    }
    #pragma unroll
    for (int i = 0; i < 4; ++i)
        *(float4*)&g_xw0[p[i]*64 + tx*4] = acc2[i];
    GDC_LAUNCH();
}

// ---------------- K2: G'0 = Nrm^T @ HW0 per (t,b), cp.async double-buffered -----
__global__ __launch_bounds__(256) void k_gmat0()
{
    const float4* nrm4 = (const float4*)g_nrmP;
    const float4* hw4  = (const float4*)g_xw0;
    extern __shared__ __align__(16) float sm[];
    int t = blockIdx.x, b = blockIdx.y;
    int tid = threadIdx.x;
    int tx = tid & 15, ty = tid >> 4;
    unsigned smb = sm32(sm);

    GDC_WAIT(); GDC_LAUNCH();
    int Kt = g_cnt[b*Tt + t];
    int rbase = (b << 10) + g_off[b*Tt + t];

    #pragma unroll
    for (int it = 0; it < 4; ++it) {
        int e = tid + it*256;
        int rr = e >> 4, kq = e & 15;
        int sz = (rr < Kt) ? 16 : 0;
        int gi = (rbase + ((rr < Kt) ? rr : 0))*16 + kq;
        cpa16(smb + (0    + rr*68 + kq*4)*4, nrm4 + gi, sz);
        cpa16(smb + (8704 + rr*68 + kq*4)*4, hw4  + gi, sz);
    }
    CP_COMMIT();

    float4 acc[4];
    #pragma unroll
    for (int i = 0; i < 4; ++i) acc[i] = make_float4(0.f,0.f,0.f,0.f);

    int nt = (Kt + 63) >> 6;
    for (int i = 0; i < nt; ++i) {
        int cur = i & 1, nxt = cur ^ 1;
        if (i + 1 < nt) {
            int r1 = (i + 1) << 6;
            #pragma unroll
            for (int it = 0; it < 4; ++it) {
                int e = tid + it*256;
                int rr = e >> 4, kq = e & 15;
                int r = r1 + rr;
                int sz = (r < Kt) ? 16 : 0;
                int gi = (rbase + ((r < Kt) ? r : 0))*16 + kq;
                cpa16(smb + (nxt*4352        + rr*68 + kq*4)*4, nrm4 + gi, sz);
                cpa16(smb + (8704 + nxt*4352 + rr*68 + kq*4)*4, hw4  + gi, sz);
            }
        }
        CP_COMMIT();
        CP_WAIT1();
        __syncthreads();

        const float* sA = sm + cur*4352;
        const float* sB = sm + 8704 + cur*4352;
        #pragma unroll 8
        for (int rr = 0; rr < 64; ++rr) {
            float4 a  = *(const float4*)&sA[rr*68 + ty*4];
            float4 bb = *(const float4*)&sB[rr*68 + tx*4];
            FMA4(acc[0], a.x, bb); FMA4(acc[1], a.y, bb);
            FMA4(acc[2], a.z, bb); FMA4(acc[3], a.w, bb);
        }
        __syncthreads();
    }
    float* Gp = &g_G[(b*Tt + t)*4096];
    #pragma unroll
    for (int i = 0; i < 4; ++i)
        *(float4*)&Gp[(ty*4 + i)*64 + tx*4] = acc[i];
}

// ---------------- K2b: M' = sum_t sigmoid(C) G' ---------------------------------
__global__ __launch_bounds__(128) void k_combine(const float* __restrict__ cont)
{
    __shared__ float s_S[Tt*Tt];
    int b = blockIdx.x, tid = threadIdx.x;
    if (tid < Tt*Tt) s_S[tid] = 1.f / (1.f + expf(-cont[tid]));
    __syncthreads();
    GDC_WAIT(); GDC_LAUNCH();
    int i4 = blockIdx.y * 128 + tid;
    const float4* G4 = (const float4*)g_G + (size_t)b*10240;
    float4*       M4 = (float4*)g_M       + (size_t)b*10240;
    float4 g[Tt];
    #pragma unroll
    for (int t = 0; t < Tt; ++t) g[t] = G4[t*1024 + i4];
    #pragma unroll
    for (int tp = 0; tp < Tt; ++tp) {
        float4 o = make_float4(0.f,0.f,0.f,0.f);
        #pragma unroll
        for (int t = 0; t < Tt; ++t) {
            float s = s_S[tp*Tt + t];
            FMA4(o, s, g[t]);
        }
        M4[tp*1024 + i4] = o;
    }
}

// ---------------- K3a: layer0 + fused G'1 accumulation --------------------------
// h1 = relu(HW0 + nrm@M'0 + b0); HW1 = h1@W1^T -> g_xw1;
// G'1[b,t] = sum_rows nrm^T @ HW1 -> g_G (overwrites G'0)
// smem: SB M' 4352 | SW W1^T 4352 | SA nrm 4352 | SXH X/HW1 4352 = 69632 B
__global__ __launch_bounds__(256, 3) void k_layer0(
    const float* __restrict__ gnn_w, const float* __restrict__ gnn_b)
{
    const float* hw = g_xw0;
    const float4* nrm4 = (const float4*)g_nrmP;
    extern __shared__ __align__(16) float sm[];
    float* s_B  = sm;
    float* s_W  = sm + 4352;
    float* s_A  = sm + 8704;
    float* s_XH = sm + 13056;
    __shared__ __align__(16) float s_bias[64];

    int t = blockIdx.x, b = blockIdx.y;
    int tid = threadIdx.x;
    int tx = tid & 15, ty = tid >> 4;

    if (tid < 64) s_bias[tid] = gnn_b[tid];
    {
        const float* Wp = gnn_w + 4096;     // W1
        #pragma unroll
        for (int it = 0; it < 16; ++it) {
            int e = tid + it*256;
            s_W[(e & 63)*68 + (e >> 6)] = Wp[e];   // W1^T [k][c]
        }
    }
    GDC_WAIT(); GDC_LAUNCH();
    int Kt = g_cnt[b*Tt + t];
    int rbase = (b << 10) + g_off[b*Tt + t];

    const float4* Mp4 = (const float4*)&g_M[(b*Tt + t)*4096];
    #pragma unroll
    for (int it = 0; it < 4; ++it) {
        int e = tid + it*256;
        *(float4*)&s_B[(e >> 4)*68 + (e & 15)*4] = Mp4[e];
    }
    float4 bias = *(const float4*)&s_bias[tx*4];
    float4 acc3[4];   // persistent G'1 accumulators
    #pragma unroll
    for (int i = 0; i < 4; ++i) acc3[i] = make_float4(0.f,0.f,0.f,0.f);
    __syncthreads();

    for (int r0 = 0; r0 < Kt; r0 += 64) {
        // stage nrm tile
        #pragma unroll
        for (int it = 0; it < 4; ++it) {
            int e = tid + it*256;
            int rr = e >> 4, kq = e & 15;
            int r = r0 + rr;
            float4 v = make_float4(0.f,0.f,0.f,0.f);
            if (r < Kt) v = nrm4[(rbase + r)*16 + kq];
            *(float4*)&s_A[rr*68 + kq*4] = v;
        }
        __syncthreads();

        // GEMM1: agg = nrm @ M'
        float4 acc[4];
        #pragma unroll
        for (int i = 0; i < 4; ++i) acc[i] = make_float4(0.f,0.f,0.f,0.f);
        #pragma unroll 8
        for (int kk = 0; kk < 64; ++kk) {
            float4 bb = *(const float4*)&s_B[kk*68 + tx*4];
            float a0 = s_A[(ty*4+0)*68 + kk];
            float a1 = s_A[(ty*4+1)*68 + kk];
            float a2 = s_A[(ty*4+2)*68 + kk];
            float a3 = s_A[(ty*4+3)*68 + kk];
            FMA4(acc[0], a0, bb); FMA4(acc[1], a1, bb);
            FMA4(acc[2], a2, bb); FMA4(acc[3], a3, bb);
        }

        // X = relu(HW0 + agg + b0) -> s_XH (natural layout)
        #pragma unroll
        for (int i = 0; i < 4; ++i) {
            int r = r0 + ty*4 + i;
            float4 x = acc[i];
            if (r < Kt) {
                float4 hv = *(const float4*)&hw[(rbase + r)*64 + tx*4];
                x.x = fmaxf(x.x + hv.x + bias.x, 0.f);
                x.y = fmaxf(x.y + hv.y + bias.y, 0.f);
                x.z = fmaxf(x.z + hv.z + bias.z, 0.f);
                x.w = fmaxf(x.w + hv.w + bias.w, 0.f);
            } else {
                x = make_float4(0.f,0.f,0.f,0.f);
            }
            *(float4*)&s_XH[(ty*4+i)*68 + tx*4] = x;
        }
        __syncthreads();

        // GEMM2: HW1 = X @ W1^T
        float4 acc2[4];
        #pragma unroll
        for (int i = 0; i < 4; ++i) acc2[i] = make_float4(0.f,0.f,0.f,0.f);
        #pragma unroll 8
        for (int kk = 0; kk < 64; ++kk) {
            float4 bb = *(const float4*)&s_W[kk*68 + tx*4];
            float a0 = s_XH[(ty*4+0)*68 + kk];
            float a1 = s_XH[(ty*4+1)*68 + kk];
            float a2 = s_XH[(ty*4+2)*68 + kk];
            float a3 = s_XH[(ty*4+3)*68 + kk];
            FMA4(acc2[0], a0, bb); FMA4(acc2[1], a1, bb);
            FMA4(acc2[2], a2, bb); FMA4(acc2[3], a3, bb);
        }
        __syncthreads();      // GEMM2 reads of s_XH done
        #pragma unroll
        for (int i = 0; i < 4; ++i) {
            int r = r0 + ty*4 + i;
            float4 v = (r < Kt) ? acc2[i] : make_float4(0.f,0.f,0.f,0.f);
            if (r < Kt)
                *(float4*)&g_xw1[(rbase + r)*64 + tx*4] = v;
            *(float4*)&s_XH[(ty*4+i)*68 + tx*4] = v;    // HW1 tile for GEMM3
        }
        __syncthreads();

        // GEMM3: G'1 += nrm^T @ HW1 (gmat-style; zero rows contribute nothing)
        #pragma unroll 8
        for (int rr = 0; rr < 64; ++rr) {
            float4 a  = *(const float4*)&s_A [rr*68 + ty*4];
            float4 bb = *(const float4*)&s_XH[rr*68 + tx*4];
            FMA4(acc3[0], a.x, bb); FMA4(acc3[1], a.y, bb);
            FMA4(acc3[2], a.z, bb); FMA4(acc3[3], a.w, bb);
        }
        __syncthreads();      // before next tile overwrites s_A / s_XH
    }

    float* Gp = &g_G[(b*Tt + t)*4096];
    #pragma unroll
    for (int i = 0; i < 4; ++i)
        *(float4*)&Gp[(ty*4 + i)*64 + tx*4] = acc3[i];
}

// ---------------- K3b: layer1 (cp.async) : h2 = relu(HW1 + nrm@M'1 + b1) --------
// smem: SB 4352 | SA0 | SA1 = 52224 B
__global__ __launch_bounds__(256) void k_layer1(
    const float* __restrict__ gnn_w, const float* __restrict__ gnn_b)
{
    const float* hw = g_xw1;
    const float4* nrm4 = (const float4*)g_nrmP;
    extern __shared__ __align__(16) float sm[];
    float* s_B = sm;
    int aoff = 4352;
    __shared__ __align__(16) float s_bias[64];
    __shared__ __align__(16) float s_csum[16][64];

    int t = blockIdx.x, b = blockIdx.y;
    int tid = threadIdx.x;
    int tx = tid & 15, ty = tid >> 4;
    unsigned smb = sm32(sm);

    if (tid < 64) s_bias[tid] = gnn_b[64 + tid];
    GDC_WAIT(); GDC_LAUNCH();
    int Kt = g_cnt[b*Tt + t];
    if (Kt == 0) return;
    int rbase = (b << 10) + g_off[b*Tt + t];

    #pragma unroll
    for (int it = 0; it < 4; ++it) {
        int e = tid + it*256;
        int rr = e >> 4, kq = e & 15;
        int sz = (rr < Kt) ? 16 : 0;
        int gi = (rbase + ((rr < Kt) ? rr : 0))*16 + kq;
        cpa16(smb + (aoff + rr*68 + kq*4)*4, nrm4 + gi, sz);
    }
    CP_COMMIT();

    const float4* Mp4 = (const float4*)&g_M[(b*Tt + t)*4096];
    #pragma unroll
    for (int it = 0; it < 4; ++it) {
        int e = tid + it*256;
        *(float4*)&s_B[(e >> 4)*68 + (e & 15)*4] = Mp4[e];
    }
    float4 psum = make_float4(0.f,0.f,0.f,0.f);
    float4 bias = *(const float4*)&s_bias[tx*4];

    int nt = (Kt + 63) >> 6;
    for (int i = 0; i < nt; ++i) {
        int cur = i & 1, nxt = cur ^ 1;
        int r0 = i << 6;
        if (i + 1 < nt) {
            int r1 = r0 + 64;
            #pragma unroll
            for (int it = 0; it < 4; ++it) {
                int e = tid + it*256;
                int rr = e >> 4, kq = e & 15;
                int r = r1 + rr;
                int sz = (r < Kt) ? 16 : 0;
                int gi = (rbase + ((r < Kt) ? r : 0))*16 + kq;
                cpa16(smb + (aoff + nxt*4352 + rr*68 + kq*4)*4, nrm4 + gi, sz);
            }
        }
        CP_COMMIT();
        CP_WAIT1();
        __syncthreads();

        float* sA = sm + aoff + cur*4352;

        float4 acc[4];
        #pragma unroll
        for (int i2 = 0; i2 < 4; ++i2) acc[i2] = make_float4(0.f,0.f,0.f,0.f);
        #pragma unroll 8
        for (int kk = 0; kk < 64; ++kk) {
            float4 bb = *(const float4*)&s_B[kk*68 + tx*4];
            float a0 = sA[(ty*4+0)*68 + kk];
            float a1 = sA[(ty*4+1)*68 + kk];
            float a2 = sA[(ty*4+2)*68 + kk];
            float a3 = sA[(ty*4+3)*68 + kk];
            FMA4(acc[0], a0, bb); FMA4(acc[1], a1, bb);
            FMA4(acc[2], a2, bb); FMA4(acc[3], a3, bb);
        }
        #pragma unroll
        for (int i2 = 0; i2 < 4; ++i2) {
            int r = r0 + ty*4 + i2;
            if (r < Kt) {
                float4 x = acc[i2];
                float4 hv = *(const float4*)&hw[(rbase + r)*64 + tx*4];
                x.x = fmaxf(x.x + hv.x + bias.x, 0.f);
                x.y = fmaxf(x.y + hv.y + bias.y, 0.f);
                x.z = fmaxf(x.z + hv.z + bias.z, 0.f);
                x.w = fmaxf(x.w + hv.w + bias.w, 0.f);
                *(float4*)&g_h2P[(rbase + r)*64 + tx*4] = x;
                psum.x += x.x; psum.y += x.y; psum.z += x.z; psum.w += x.w;
            }
        }
        __syncthreads();
    }

    *(float4*)&s_csum[ty][tx*4] = psum;
    __syncthreads();
    if (tid < 64) {
        float s = 0.f;
        #pragma unroll
        for (int q = 0; q < 16; ++q) s += s_csum[q][tid];
        atomicAdd(&g_ctx[b*64 + tid], s);
    }
}

// ---------------- K4: head (+GRU per block, K=64, gathers h2P via pos) ----------
__global__ __launch_bounds__(256) void k_head(
    const float* __restrict__ prev, const float* __restrict__ wih,
    const float* __restrict__ whh,  const float* __restrict__ bih,
    const float* __restrict__ bhh,
    const float* __restrict__ w1, const float* __restrict__ b1,
    const float* __restrict__ w2, const float* __restrict__ b2,
    float* __restrict__ out)
{
    __shared__ __align__(16) float s_X[64*68];
    __shared__ __align__(16) float s_W[64*68];
    __shared__ __align__(16) float s_g[320];
    __shared__ __align__(16) float s_hs[64];
    __shared__ __align__(16) float s_w2[64];
    __shared__ int s_pos[64];
    int tid = threadIdx.x;
    int tx = tid & 15, ty = tid >> 4;
    int u = blockIdx.x;
    int base = u << 6;
    int b = u >> 4;

    #pragma unroll
    for (int it = 0; it < 16; ++it) {
        int e = tid + it*256;
        int j = e >> 6, k = e & 63;
        s_W[k*68 + j] = w1[j*96 + k];
    }
    if (tid < 64) s_w2[tid] = w2[tid];
    GDC_WAIT();
    if (tid < 64)       s_g[tid] = g_ctx[b*64 + tid] * (1.f/1024.f);
    else if (tid < 96)  s_g[tid] = prev[b*32 + (tid - 64)];
    else if (tid < 160) s_pos[tid - 96] = g_pos[base + (tid - 96)];
    __syncthreads();

    const float4* h24 = (const float4*)g_h2P;
    #pragma unroll
    for (int it = 0; it < 4; ++it) {
        int e = tid + it*256;
        int rr = e >> 4, kq = e & 15;
        *(float4*)&s_X[rr*68 + kq*4] = h24[s_pos[rr]*16 + kq];
    }
    if (tid < 96) {
        float gi = bih[tid], gh = bhh[tid];
        #pragma unroll 16
        for (int k = 0; k < 64; ++k) gi += s_g[k] * wih[tid*64 + k];
        #pragma unroll 16
        for (int k = 0; k < 32; ++k) gh += s_g[64 + k] * whh[tid*32 + k];
        s_g[96 + tid] = gi; s_g[192 + tid] = gh;
    }
    __syncthreads();
    if (tid < 32) {
        float r  = 1.f / (1.f + expf(-(s_g[96  + tid] + s_g[192 + tid])));
        float z  = 1.f / (1.f + expf(-(s_g[128 + tid] + s_g[224 + tid])));
        float nn = tanhf(s_g[160 + tid] + r * s_g[256 + tid]);
        float ns = (1.f - z)*nn + z*s_g[64 + tid];
        s_g[288 + tid] = ns;
        if ((u & 15) == 0) out[Bb*Nn + b*32 + tid] = ns;
    }
    __syncthreads();
    if (tid < 64) {
        float v = b1[tid];
        #pragma unroll
        for (int k = 0; k < 32; ++k) v += w1[tid*96 + 64 + k] * s_g[288 + k];
        s_hs[tid] = v;
    }
    __syncthreads();

    float4 hs = *(const float4*)&s_hs[tx*4];
    float4 acc[4] = {hs, hs, hs, hs};
    #pragma unroll 8
    for (int kk = 0; kk < 64; ++kk) {
        float4 bb = *(const float4*)&s_W[kk*68 + tx*4];
        float a0 = s_X[(ty*4+0)*68 + kk];
        float a1 = s_X[(ty*4+1)*68 + kk];
        float a2 = s_X[(ty*4+2)*68 + kk];
        float a3 = s_X[(ty*4+3)*68 + kk];
        FMA4(acc[0], a0, bb); FMA4(acc[1], a1, bb);
        FMA4(acc[2], a2, bb); FMA4(acc[3], a3, bb);
    }
    float4 w2v = *(const float4*)&s_w2[tx*4];
    float b2v = b2[0];
    #pragma unroll
    for (int i = 0; i < 4; ++i) {
        float y = fmaxf(acc[i].x, 0.f)*w2v.x + fmaxf(acc[i].y, 0.f)*w2v.y
                + fmaxf(acc[i].z, 0.f)*w2v.z + fmaxf(acc[i].w, 0.f)*w2v.w;
        #pragma unroll
        for (int o = 8; o > 0; o >>= 1) y += __shfl_xor_sync(0xffffffffu, y, o);
        if (tx == 0) out[base + ty*4 + i] = y + b2v;
    }
}

// ---------------- launch ---------------------------------------------------------
extern "C" void kernel_launch(void* const* d_in, const int* in_sizes, int n_in,
                              void* d_out, int out_size)
{
    const float* tf    = (const float*)d_in[0];
    const int*   types = (const int*)  d_in[1];
    const float* prev  = (const float*)d_in[2];
    const float* ew1   = (const float*)d_in[3];
    const float* eb1   = (const float*)d_in[4];
    const float* ew2   = (const float*)d_in[5];
    const float* eb2   = (const float*)d_in[6];
    const float* cont  = (const float*)d_in[7];
    const float* gw    = (const float*)d_in[8];
    const float* gb    = (const float*)d_in[9];
    const float* wih   = (const float*)d_in[10];
    const float* whh   = (const float*)d_in[11];
    const float* bih   = (const float*)d_in[12];
    const float* bhh   = (const float*)d_in[13];
    const float* hw1   = (const float*)d_in[14];
    const float* hb1   = (const float*)d_in[15];
    const float* hw2   = (const float*)d_in[16];
    const float* hb2   = (const float*)d_in[17];
    float* out = (float*)d_out;

    cudaFuncSetAttribute(k_gmat0,  cudaFuncAttributeMaxDynamicSharedMemorySize, 69632);
    cudaFuncSetAttribute(k_layer0, cudaFuncAttributeMaxDynamicSharedMemorySize, 69632);
    cudaFuncSetAttribute(k_layer1, cudaFuncAttributeMaxDynamicSharedMemorySize, 52224);

    cudaLaunchAttribute at;
    at.id = cudaLaunchAttributeProgrammaticStreamSerialization;
    at.val.programmaticStreamSerializationAllowed = 1;
    cudaLaunchConfig_t cfg = {};
    cfg.attrs = &at;
    cfg.numAttrs = 1;
    cfg.stream = 0;

    k_enc<<<1024, 256>>>(tf, types, ew1, eb1, ew2, eb2, gw);

    cfg.gridDim = dim3(Tt, Bb); cfg.blockDim = dim3(256); cfg.dynamicSmemBytes = 69632;
    cudaLaunchKernelEx(&cfg, k_gmat0);
    cfg.gridDim = dim3(Bb, 8); cfg.blockDim = dim3(128); cfg.dynamicSmemBytes = 0;
    cudaLaunchKernelEx(&cfg, k_combine, cont);
    cfg.gridDim = dim3(Tt, Bb); cfg.blockDim = dim3(256); cfg.dynamicSmemBytes = 69632;
    cudaLaunchKernelEx(&cfg, k_layer0, gw, gb);
    cfg.gridDim = dim3(Bb, 8); cfg.blockDim = dim3(128); cfg.dynamicSmemBytes = 0;
    cudaLaunchKernelEx(&cfg, k_combine, cont);
    cfg.gridDim = dim3(Tt, Bb); cfg.blockDim = dim3(256); cfg.dynamicSmemBytes = 52224;
    cudaLaunchKernelEx(&cfg, k_layer1, gw, gb);
    cfg.gridDim = dim3(1024); cfg.blockDim = dim3(256); cfg.dynamicSmemBytes = 0;
    cudaLaunchKernelEx(&cfg, k_head, prev, wih, whh, bih, bhh,
                       hw1, hb1, hw2, hb2, out);
}